// round 4
// baseline (speedup 1.0000x reference)
#include <cuda_runtime.h>
#include <math.h>

#define B_ 16
#define C_ 256
#define H_ 128
#define W_ 128
#define PLANE (H_ * W_)          // 16384 elements per (b,c) plane
#define NPLANES (B_ * C_)        // 4096
#define DIMH 128                 // dim/2

#define CHUNKB 4                 // batches per chunk (64 MB < 126 MB L2)
#define NCHUNK (B_ / CHUNKB)     // 4
#define CPLANES (CHUNKB * C_)    // 1024 planes per chunk

__device__ float g_pooled[NPLANES];
__device__ float g_scale[NPLANES];
__device__ int   g_cnt[B_];      // zero-init at load; reset by MLP block each run

__device__ __forceinline__ float sigmoidf_(float v) {
    return 1.0f / (1.0f + expf(-v));
}
__device__ __forceinline__ float warp_sum(float v) {
#pragma unroll
    for (int off = 16; off > 0; off >>= 1)
        v += __shfl_xor_sync(0xFFFFFFFFu, v, off);
    return v;
}

// ---------------------------------------------------------------------------
// Pool a chunk of 1024 planes (one block per plane). The block that completes
// its batch's 256 planes (atomic counter) computes the batch MLP inline:
//   h     = relu(pooled @ W1^T + b1)
//   scale = sigmoid(h @ W2^T + b2) + sigmoid(pooled @ Wc^T + bc)
// ---------------------------------------------------------------------------
__global__ __launch_bounds__(256) void pool_chunk_kernel(
    const float* __restrict__ x, int base_plane,
    const float* __restrict__ W1, const float* __restrict__ b1,
    const float* __restrict__ W2, const float* __restrict__ b2,
    const float* __restrict__ Wc, const float* __restrict__ bc) {
    const int plane = base_plane + blockIdx.x;
    const int b     = plane >> 8;         // C_ = 256
    const int t     = threadIdx.x;
    const int wid   = t >> 5;
    const int lane  = t & 31;

    // ---- pool one plane ----
    const float4* __restrict__ p =
        reinterpret_cast<const float4*>(x) + (size_t)plane * (PLANE / 4);
    float acc = 0.f;
#pragma unroll
    for (int k = 0; k < PLANE / 4 / 256; ++k) {
        float4 v = p[t + k * 256];
        acc += (v.x + v.y) + (v.z + v.w);
    }
    acc = warp_sum(acc);

    __shared__ float warp_sums[8];
    __shared__ int   s_last;
    if (lane == 0) warp_sums[wid] = acc;
    __syncthreads();
    if (t == 0) {
        float s = 0.f;
#pragma unroll
        for (int w = 0; w < 8; ++w) s += warp_sums[w];
        g_pooled[plane] = s * (1.0f / PLANE);
        __threadfence();                       // publish before arrival
        int old = atomicAdd(&g_cnt[b], 1);
        s_last = (old == C_ - 1);
    }
    __syncthreads();
    if (!s_last) return;

    // ---- last block of batch b: compute the MLP for all 256 channels ----
    __threadfence();                           // order loads after the atomic
    __shared__ float sp[C_];
    __shared__ float sh[DIMH];
    sp[t] = __ldcg(&g_pooled[b * C_ + t]);     // bypass (possibly stale) L1
    __syncthreads();

    // hidden: 8 warps x 16 outputs, warp-dot (coalesced)
#pragma unroll
    for (int i = 0; i < DIMH / 8; ++i) {
        const int o = wid * 16 + i;
        const float* __restrict__ row = W1 + o * C_;
        float a = 0.f;
#pragma unroll
        for (int k = 0; k < C_ / 32; ++k)
            a = fmaf(sp[lane + 32 * k], row[lane + 32 * k], a);
        a = warp_sum(a);
        if (lane == 0) sh[o] = fmaxf(a + b1[o], 0.0f);
    }
    __syncthreads();

    // outputs: 8 warps x 32 channels, warp-dot
#pragma unroll 4
    for (int i = 0; i < 32; ++i) {
        const int o = wid * 32 + i;
        const float* __restrict__ row2 = W2 + o * DIMH;
        float accw = 0.f;
#pragma unroll
        for (int k = 0; k < DIMH / 32; ++k)
            accw = fmaf(sh[lane + 32 * k], row2[lane + 32 * k], accw);
        const float* __restrict__ rowc = Wc + o * C_;
        float accg = 0.f;
#pragma unroll
        for (int k = 0; k < C_ / 32; ++k)
            accg = fmaf(sp[lane + 32 * k], rowc[lane + 32 * k], accg);
        accw = warp_sum(accw);
        accg = warp_sum(accg);
        if (lane == 0)
            g_scale[b * C_ + o] = sigmoidf_(accw + b2[o]) + sigmoidf_(accg + bc[o]);
    }

    if (t == 0) g_cnt[b] = 0;                  // restore for next graph replay
}

// ---------------------------------------------------------------------------
// Scale a chunk: out = x * scale[plane]. x chunk is L2-resident from the
// immediately preceding pool launch; writes are streaming (evict-first).
// ---------------------------------------------------------------------------
__global__ __launch_bounds__(256) void scale_chunk_kernel(
    const float* __restrict__ x, float* __restrict__ out, int base_plane) {
    const int plane = base_plane + blockIdx.x;
    const float s = g_scale[plane];
    const float4* __restrict__ pin =
        reinterpret_cast<const float4*>(x) + (size_t)plane * (PLANE / 4);
    float4* __restrict__ pout =
        reinterpret_cast<float4*>(out) + (size_t)plane * (PLANE / 4);
    const int t = threadIdx.x;

#pragma unroll
    for (int k = 0; k < PLANE / 4 / 256; ++k) {
        float4 v = pin[t + k * 256];
        v.x *= s; v.y *= s; v.z *= s; v.w *= s;
        __stcs(&pout[t + k * 256], v);
    }
}

// ---------------------------------------------------------------------------
extern "C" void kernel_launch(void* const* d_in, const int* in_sizes, int n_in,
                              void* d_out, int out_size) {
    const float* x  = (const float*)d_in[0];
    const float* W1 = (const float*)d_in[1];
    const float* b1 = (const float*)d_in[2];
    const float* W2 = (const float*)d_in[3];
    const float* b2 = (const float*)d_in[4];
    const float* Wc = (const float*)d_in[5];
    const float* bc = (const float*)d_in[6];
    float* out = (float*)d_out;

    for (int c = 0; c < NCHUNK; ++c) {
        const int base = c * CPLANES;
        pool_chunk_kernel<<<CPLANES, 256>>>(x, base, W1, b1, W2, b2, Wc, bc);
        scale_chunk_kernel<<<CPLANES, 256>>>(x, out, base);
    }
}

// round 5
// speedup vs baseline: 1.3445x; 1.3445x over previous
#include <cuda_runtime.h>
#include <math.h>

#define B_ 16
#define C_ 256
#define PLANE 16384               // H*W floats per (b,c) plane
#define NPLANES (B_ * C_)         // 4096
#define DIMH 128

#define THREADS 256
#define BLK_ELEMS 8192            // half a plane per block (32 KB smem)
#define BLKS_PER_BATCH 512
#define NBLK (B_ * BLKS_PER_BATCH)   // 8192
#define F4PT (BLK_ELEMS / 4 / THREADS) // 8 float4 per thread

// Cross-block scratch (zero at module load; counters self-reset each run)
__device__ float g_bsum[NBLK];        // per-block partial sums
__device__ float g_h[B_ * DIMH];      // hidden layer per batch
__device__ int   g_cnt1[B_];          // pooled-ready arrivals (512)
__device__ int   g_cnt2[B_];          // hidden-ready arrivals (128)
__device__ int   g_done[B_];          // completion arrivals (512) -> reset

__device__ __forceinline__ float sigmoidf_(float v) {
    return 1.0f / (1.0f + expf(-v));
}
__device__ __forceinline__ float warp_sum(float v) {
#pragma unroll
    for (int off = 16; off > 0; off >>= 1)
        v += __shfl_xor_sync(0xFFFFFFFFu, v, off);
    return v;
}

__global__ __launch_bounds__(THREADS) void fused_kernel(
    const float* __restrict__ x, float* __restrict__ out,
    const float* __restrict__ W1, const float* __restrict__ b1,
    const float* __restrict__ W2, const float* __restrict__ b2,
    const float* __restrict__ Wc, const float* __restrict__ bc) {

    __shared__ float xs[BLK_ELEMS];   // 32 KB staging of this block's x slice
    __shared__ float red_a[8];
    __shared__ float red_b[8];
    __shared__ float s_scale;

    const int bid   = blockIdx.x;
    const int t     = threadIdx.x;
    const int wid   = t >> 5;
    const int lane  = t & 31;
    const int batch = bid >> 9;                 // /512
    const int local = bid & (BLKS_PER_BATCH - 1);
    const int c     = (bid >> 1) & (C_ - 1);    // channel of this half-plane

    const float4* __restrict__ pin =
        reinterpret_cast<const float4*>(x) + (size_t)bid * (BLK_ELEMS / 4);
    float4* __restrict__ pout =
        reinterpret_cast<float4*>(out) + (size_t)bid * (BLK_ELEMS / 4);

    // ---- Phase A: stream x slice into SMEM, accumulate partial sum ----
    float acc = 0.f;
#pragma unroll
    for (int k = 0; k < F4PT; ++k) {
        float4 v = pin[t + THREADS * k];
        reinterpret_cast<float4*>(xs)[t + THREADS * k] = v;
        acc += (v.x + v.y) + (v.z + v.w);
    }
    acc = warp_sum(acc);
    if (lane == 0) red_a[wid] = acc;
    __syncthreads();
    if (t == 0) {
        float s = 0.f;
#pragma unroll
        for (int w = 0; w < 8; ++w) s += red_a[w];
        g_bsum[bid] = s;
        __threadfence();
        atomicAdd(&g_cnt1[batch], 1);
    }

    // ---- Phase B: first 128 blocks of the batch compute the hidden layer ----
    if (local < DIMH) {
        if (t == 0) {
            while (((volatile int*)g_cnt1)[batch] < BLKS_PER_BATCH) __nanosleep(64);
        }
        __syncthreads();
        __threadfence();
        // pooled[t] for this batch: pair of block partials (fixed order -> deterministic)
        float sp_t = (__ldcg(&g_bsum[batch * BLKS_PER_BATCH + 2 * t]) +
                      __ldcg(&g_bsum[batch * BLKS_PER_BATCH + 2 * t + 1])) * (1.0f / PLANE);
        float p = sp_t * __ldg(&W1[local * C_ + t]);   // coalesced across t
        p = warp_sum(p);
        if (lane == 0) red_a[wid] = p;
        __syncthreads();
        if (t == 0) {
            float s = 0.f;
#pragma unroll
            for (int w = 0; w < 8; ++w) s += red_a[w];
            g_h[batch * DIMH + local] = fmaxf(s + __ldg(&b1[local]), 0.0f);
            __threadfence();
            atomicAdd(&g_cnt2[batch], 1);
        }
        __syncthreads();
    }

    // ---- Phase C: wait for hidden, compute this channel's scale ----
    if (t == 0) {
        while (((volatile int*)g_cnt2)[batch] < DIMH) __nanosleep(64);
    }
    __syncthreads();
    __threadfence();

    float sp_t = (__ldcg(&g_bsum[batch * BLKS_PER_BATCH + 2 * t]) +
                  __ldcg(&g_bsum[batch * BLKS_PER_BATCH + 2 * t + 1])) * (1.0f / PLANE);
    float pg = sp_t * __ldg(&Wc[c * C_ + t]);                         // gate dot (256)
    float pw = (t < DIMH)
             ? __ldcg(&g_h[batch * DIMH + t]) * __ldg(&W2[c * DIMH + t])  // weight dot (128)
             : 0.f;
    pg = warp_sum(pg);
    pw = warp_sum(pw);
    if (lane == 0) { red_a[wid] = pg; red_b[wid] = pw; }
    __syncthreads();
    if (t == 0) {
        float sg = 0.f, sw = 0.f;
#pragma unroll
        for (int w = 0; w < 8; ++w) { sg += red_a[w]; sw += red_b[w]; }
        s_scale = sigmoidf_(sw + __ldg(&b2[c])) + sigmoidf_(sg + __ldg(&bc[c]));
    }
    __syncthreads();

    // ---- Phase D: multiply SMEM slice, stream out (no second DRAM read) ----
    const float s = s_scale;
#pragma unroll
    for (int k = 0; k < F4PT; ++k) {
        float4 v = reinterpret_cast<const float4*>(xs)[t + THREADS * k];
        v.x *= s; v.y *= s; v.z *= s; v.w *= s;
        __stcs(&pout[t + THREADS * k], v);
    }

    // ---- Cleanup: last finisher resets the batch's counters for replay ----
    if (t == 0) {
        int d = atomicAdd(&g_done[batch], 1);
        if (d == BLKS_PER_BATCH - 1) {
            g_cnt1[batch] = 0;
            g_cnt2[batch] = 0;
            __threadfence();
            g_done[batch] = 0;
        }
    }
}

extern "C" void kernel_launch(void* const* d_in, const int* in_sizes, int n_in,
                              void* d_out, int out_size) {
    const float* x  = (const float*)d_in[0];
    const float* W1 = (const float*)d_in[1];
    const float* b1 = (const float*)d_in[2];
    const float* W2 = (const float*)d_in[3];
    const float* b2 = (const float*)d_in[4];
    const float* Wc = (const float*)d_in[5];
    const float* bc = (const float*)d_in[6];
    float* out = (float*)d_out;

    fused_kernel<<<NBLK, THREADS>>>(x, out, W1, b1, W2, b2, Wc, bc);
}

// round 8
// speedup vs baseline: 1.4091x; 1.0481x over previous
#include <cuda_runtime.h>
#include <math.h>

#define B_ 16
#define C_ 256
#define PLANE 16384                // H*W floats per (b,c) plane
#define NPLANES (B_ * C_)          // 4096
#define DIMH 128

#define CHUNK_PLANES 512           // 2 batches per chunk (32 MB)
#define NCHUNKS (NPLANES / CHUNK_PLANES)   // 8
#define THREADS 256
#define F4PP (PLANE / 4 / THREADS) // 16 float4 per thread per plane

__device__ float g_pooled[NPLANES];

__device__ __forceinline__ float sigmoidf_(float v) {
    return 1.0f / (1.0f + expf(-v));
}
__device__ __forceinline__ float warp_sum(float v) {
#pragma unroll
    for (int off = 16; off > 0; off >>= 1)
        v += __shfl_xor_sync(0xFFFFFFFFu, v, off);
    return v;
}

// ---------------------------------------------------------------------------
// Pool one plane (block-level). Default caching: plane lines retained in L2
// for the scale pass that follows in the next launch.
// ---------------------------------------------------------------------------
__device__ __forceinline__ void pool_plane(const float* __restrict__ x, int plane) {
    const int t = threadIdx.x;
    const float4* __restrict__ p =
        reinterpret_cast<const float4*>(x) + (size_t)plane * (PLANE / 4);

    float acc = 0.f;
#pragma unroll
    for (int k = 0; k < F4PP; ++k) {
        float4 v = p[t + THREADS * k];
        acc += (v.x + v.y) + (v.z + v.w);
    }
    acc = warp_sum(acc);

    __shared__ float red[8];
    if ((t & 31) == 0) red[t >> 5] = acc;
    __syncthreads();
    if (t == 0) {
        float s = 0.f;
#pragma unroll
        for (int w = 0; w < 8; ++w) s += red[w];
        g_pooled[plane] = s * (1.0f / PLANE);
    }
}

// ---------------------------------------------------------------------------
// Scale one plane (block-level). The block derives its channel's scale from
// g_pooled via an inline redundant MLP (weights L2-hot, ~200 FLOP/thread),
// then streams the plane: x read via __ldcs (L2 hit, evict-first), out
// written via __stcs (streaming).
// ---------------------------------------------------------------------------
__device__ __forceinline__ void scale_plane(
    const float* __restrict__ x, float* __restrict__ out, int plane,
    const float* __restrict__ W1, const float* __restrict__ b1,
    const float* __restrict__ W2, const float* __restrict__ b2,
    const float* __restrict__ Wc, const float* __restrict__ bc) {

    const int t    = threadIdx.x;
    const int wid  = t >> 5;
    const int lane = t & 31;
    const int b    = plane >> 8;      // C_ = 256
    const int c    = plane & (C_ - 1);

    __shared__ float sp[C_];
    __shared__ float sh[DIMH];
    __shared__ float red_a[8];
    __shared__ float red_b[8];
    __shared__ float s_scale;

    sp[t] = g_pooled[b * C_ + t];
    __syncthreads();

    // hidden layer: 8 warps x 16 outputs, warp-dot (coalesced)
#pragma unroll
    for (int i = 0; i < DIMH / 8; ++i) {
        const int o = wid * 16 + i;
        const float* __restrict__ row = W1 + o * C_;
        float a = 0.f;
#pragma unroll
        for (int k = 0; k < C_ / 32; ++k)
            a = fmaf(sp[lane + 32 * k], __ldg(&row[lane + 32 * k]), a);
        a = warp_sum(a);
        if (lane == 0) sh[o] = fmaxf(a + __ldg(&b1[o]), 0.0f);
    }
    __syncthreads();

    // this channel's two dots
    float pw = (t < DIMH) ? sh[t] * __ldg(&W2[c * DIMH + t]) : 0.f;
    float pg = sp[t] * __ldg(&Wc[c * C_ + t]);
    pw = warp_sum(pw);
    pg = warp_sum(pg);
    if (lane == 0) { red_a[wid] = pw; red_b[wid] = pg; }
    __syncthreads();
    if (t == 0) {
        float sw = 0.f, sg = 0.f;
#pragma unroll
        for (int w = 0; w < 8; ++w) { sw += red_a[w]; sg += red_b[w]; }
        s_scale = sigmoidf_(sw + __ldg(&b2[c])) + sigmoidf_(sg + __ldg(&bc[c]));
    }
    __syncthreads();
    const float s = s_scale;

    const float4* __restrict__ pin =
        reinterpret_cast<const float4*>(x) + (size_t)plane * (PLANE / 4);
    float4* __restrict__ pout =
        reinterpret_cast<float4*>(out) + (size_t)plane * (PLANE / 4);
#pragma unroll
    for (int k = 0; k < F4PP; ++k) {
        float4 v = __ldcs(&pin[t + THREADS * k]);
        v.x *= s; v.y *= s; v.z *= s; v.w *= s;
        __stcs(&pout[t + THREADS * k], v);
    }
}

// ---------------------------------------------------------------------------
__global__ __launch_bounds__(THREADS) void pool_kernel(
    const float* __restrict__ x, int base) {
    pool_plane(x, base + blockIdx.x);
}

__global__ __launch_bounds__(THREADS) void scale_kernel(
    const float* __restrict__ x, float* __restrict__ out, int base,
    const float* __restrict__ W1, const float* __restrict__ b1,
    const float* __restrict__ W2, const float* __restrict__ b2,
    const float* __restrict__ Wc, const float* __restrict__ bc) {
    scale_plane(x, out, base + blockIdx.x, W1, b1, W2, b2, Wc, bc);
}

// combo: pool(chunk i) on low block ids (dispatched first), scale(chunk i-1)
// on high block ids — overlaps next chunk's DRAM reads with this chunk's writes.
__global__ __launch_bounds__(THREADS) void combo_kernel(
    const float* __restrict__ x, float* __restrict__ out,
    int scale_base, int pool_base,
    const float* __restrict__ W1, const float* __restrict__ b1,
    const float* __restrict__ W2, const float* __restrict__ b2,
    const float* __restrict__ Wc, const float* __restrict__ bc) {
    const int bid = blockIdx.x;
    if (bid < CHUNK_PLANES)
        pool_plane(x, pool_base + bid);
    else
        scale_plane(x, out, scale_base + (bid - CHUNK_PLANES),
                    W1, b1, W2, b2, Wc, bc);
}

// ---------------------------------------------------------------------------
extern "C" void kernel_launch(void* const* d_in, const int* in_sizes, int n_in,
                              void* d_out, int out_size) {
    const float* x  = (const float*)d_in[0];
    const float* W1 = (const float*)d_in[1];
    const float* b1 = (const float*)d_in[2];
    const float* W2 = (const float*)d_in[3];
    const float* b2 = (const float*)d_in[4];
    const float* Wc = (const float*)d_in[5];
    const float* bc = (const float*)d_in[6];
    float* out = (float*)d_out;

    pool_kernel<<<CHUNK_PLANES, THREADS>>>(x, 0);

    combo_kernel<<<2 * CHUNK_PLANES, THREADS>>>(x, out,    0,  512, W1, b1, W2, b2, Wc, bc);
    combo_kernel<<<2 * CHUNK_PLANES, THREADS>>>(x, out,  512, 1024, W1, b1, W2, b2, Wc, bc);
    combo_kernel<<<2 * CHUNK_PLANES, THREADS>>>(x, out, 1024, 1536, W1, b1, W2, b2, Wc, bc);
    combo_kernel<<<2 * CHUNK_PLANES, THREADS>>>(x, out, 1536, 2048, W1, b1, W2, b2, Wc, bc);
    combo_kernel<<<2 * CHUNK_PLANES, THREADS>>>(x, out, 2048, 2560, W1, b1, W2, b2, Wc, bc);
    combo_kernel<<<2 * CHUNK_PLANES, THREADS>>>(x, out, 2560, 3072, W1, b1, W2, b2, Wc, bc);
    combo_kernel<<<2 * CHUNK_PLANES, THREADS>>>(x, out, 3072, 3584, W1, b1, W2, b2, Wc, bc);

    scale_kernel<<<CHUNK_PLANES, THREADS>>>(x, out, 3584, W1, b1, W2, b2, Wc, bc);
}